// round 11
// baseline (speedup 1.0000x reference)
#include <cuda_runtime.h>

// ---------------------------------------------------------------------------
// Bit-exact fused SNN kernel, v9: R7 structure + idle-thread x prefetch.
// Phase A: warp0 lanes0-9 FC(t-1) | threads 32-227 stage1(t) | threads
// 228-255 prefetch x(t+1) (LDG.128 + scattered STS into alternate buffer).
// Phase B: pure stage2. Double-buffered x; no serial x-load anywhere.
// PROTECTED arithmetic (rel_err == 0.0 invariant):
//   conv: per-output sequential FMA in (ky, kx, ic) order
//   FC:   sequential FMA q = 0..799
//   LIF:  m' = fsub(fma(0.95, m, cur), reset)
//   pool-then-bias
// FFMA2 = two INDEPENDENT IEEE fma.rn; pairing never mixes chains.
// ---------------------------------------------------------------------------

#define T_STEPS 100
#define BATCH   256

typedef unsigned long long u64;

// smem layout (float offsets)
constexpr int OFF_W1P = 0;       // paired w1 [oc][ry-1][kx][4]      = 960
constexpr int OFF_B1  = 960;     // 12 (+4 pad)
constexpr int OFF_W2  = 976;     // w2 cl [32][25][12]               = 9600
constexpr int OFF_B2  = 10576;   // 32
constexpr int OFF_W3  = 10608;   // [10][804]                        = 8040
constexpr int OFF_B3  = 18648;   // 12
constexpr int OFF_X0  = 18660;   // x cl [32 rows][66]               = 2112
constexpr int OFF_X1  = 20772;   // x cl [32 rows][66]               = 2112
constexpr int OFF_S1A = 22884;   // spk1 A [col14][rp7][ic12][2]     = 2352
constexpr int OFF_S1B = 25236;   // spk1 B [col14][rp6][ic12][2]     = 2016
constexpr int OFF_S2  = 27252;   // 800 (oc*25 + i*5 + j)
constexpr int SMEM_FLOATS = 28052;
constexpr int SMEM_BYTES  = SMEM_FLOATS * 4;

__device__ __forceinline__ u64 pack2(float lo, float hi) {
    u64 r;
    asm("mov.b64 %0, {%1, %2};" : "=l"(r) : "f"(lo), "f"(hi));
    return r;
}
__device__ __forceinline__ void unpack2(float& lo, float& hi, u64 v) {
    asm("mov.b64 {%0, %1}, %2;" : "=f"(lo), "=f"(hi) : "l"(v));
}
// d.lo = fma.rn(a.lo, b.lo, d.lo); d.hi = fma.rn(a.hi, b.hi, d.hi)
__device__ __forceinline__ void ffma2(u64& d, u64 a, u64 b) {
    asm("fma.rn.f32x2 %0, %1, %2, %0;" : "+l"(d) : "l"(a), "l"(b));
}

__device__ __forceinline__ float lif_step(float& mem, float cur) {
    float reset = (mem > 1.0f) ? 1.0f : 0.0f;
    float mn = __fsub_rn(__fmaf_rn(0.95f, mem, cur), reset);
    mem = mn;
    return (mn > 1.0f) ? 1.0f : 0.0f;
}

__device__ __forceinline__ void fc_stage(const float* __restrict__ s,
                                         float& mem3, int t, int b, int k,
                                         float* __restrict__ out) {
    const float4* wr = reinterpret_cast<const float4*>(s + OFF_W3 + k * 804);
    const float4* xv = reinterpret_cast<const float4*>(s + OFF_S2);
    float acc = 0.f;
    #pragma unroll 4
    for (int q = 0; q < 200; q++) {
        float4 w = wr[q], x = xv[q];
        acc = fmaf(x.x, w.x, acc);
        acc = fmaf(x.y, w.y, acc);
        acc = fmaf(x.z, w.z, acc);
        acc = fmaf(x.w, w.w, acc);
    }
    float cur = __fadd_rn(acc, s[OFF_B3 + k]);
    out[((long long)t * BATCH + b) * 10 + k] = lif_step(mem3, cur);
}

// scatter one float4 (flat x elements 4q..4q+3) into channels-last buffer
__device__ __forceinline__ void x_scatter(float* __restrict__ xb,
                                          int q, float4 v) {
    int base = q * 4;
    int ic = base >> 10, pos = base & 1023;
    int r = pos >> 5, c = pos & 31;
    float* p = xb + r * 66 + c * 2 + ic;
    p[0] = v.x; p[2] = v.y; p[4] = v.z; p[6] = v.w;
}

__global__ void __launch_bounds__(256, 2) snn_kernel(
    const float* __restrict__ x,
    const float* __restrict__ W1, const float* __restrict__ b1,
    const float* __restrict__ W2, const float* __restrict__ b2,
    const float* __restrict__ W3, const float* __restrict__ b3,
    float* __restrict__ out)
{
    extern __shared__ float s[];
    const int b    = blockIdx.x;
    const int tid  = threadIdx.x;
    const int lane = tid & 31;
    const int w    = tid >> 5;

    // --- weights -> smem ---
    // paired conv1 weights: [oc][ry-1][kx][{(ry,ic0),(ry-1,ic0),(ry,ic1),(ry-1,ic1)}]
    for (int i = tid; i < 960; i += 256) {
        int q = i & 3, idx = i >> 2;
        int kx = idx % 5, ryp = (idx / 5) % 4, oc = idx / 20;
        int ry = ryp + 1;
        int ic = q >> 1;
        int useKy = (q & 1) ? (ry - 1) : ry;
        s[OFF_W1P + i] = W1[oc * 50 + ic * 25 + useKy * 5 + kx];
    }
    for (int i = tid; i < 9600; i += 256) {
        int oc = i / 300, r = i % 300, ic = r / 25, k = r % 25;
        s[OFF_W2 + oc * 300 + k * 12 + ic] = W2[i];
    }
    for (int i = tid; i < 8000; i += 256) {
        int k = i / 800, q = i % 800;
        s[OFF_W3 + k * 804 + q] = W3[i];
    }
    for (int i = tid; i < 12; i += 256) s[OFF_B1 + i] = b1[i];
    for (int i = tid; i < 32; i += 256) s[OFF_B2 + i] = b2[i];
    for (int i = tid; i < 12; i += 256) s[OFF_B3 + i] = (i < 10) ? b3[i] : 0.f;

    // preload x(t=0) into buffer 0 (synchronous, all threads)
    {
        const float4* gx4 = reinterpret_cast<const float4*>(
            x + (long long)b * 2048);
        x_scatter(s + OFF_X0, tid, gx4[tid]);
        x_scatter(s + OFF_X0, tid + 256, gx4[tid + 256]);
    }
    __syncthreads();

    float mem1r[12];
    #pragma unroll
    for (int k = 0; k < 12; k++) mem1r[k] = 0.f;
    float mem2r[4];
    #pragma unroll
    for (int k = 0; k < 4; k++) mem2r[k] = 0.f;
    float mem3r = 0.f;

    // stage2 positions: m<3 -> p = 8m + w; m=3 -> p=24, warp 7 only
    const bool has4 = (w == 7);
    int pim[4], pjm[4];
    #pragma unroll
    for (int m = 0; m < 4; m++) {
        int p = (m < 3) ? (8 * m + w) : 24;
        pim[m] = p / 5;
        pjm[m] = p % 5;
    }

    for (int t = 0; t < T_STEPS; t++) {
        const float* xs = s + ((t & 1) ? OFF_X1 : OFF_X0);

        // ===== phase A: FC(t-1) | stage1(t) | x(t+1) prefetch ==============
        if (w == 0) {
            if (t > 0 && lane < 10) fc_stage(s, mem3r, t - 1, b, lane, out);
        } else if (tid < 228) {
            const int task = tid - 32;
            const int ocg = task & 1;
            const int pos = task >> 1;
            const int i1 = pos / 7, jp = pos % 7;
            const int cb = 4 * jp;
            const int ocb = ocg * 6;

            // --- ry = 0: scalar, side0 (conv row 2i1, ky=0) ---
            float a0s[24];
            #pragma unroll
            for (int k = 0; k < 24; k++) a0s[k] = 0.f;
            {
                const float2* xr = reinterpret_cast<const float2*>(
                    xs + (2 * i1) * 66 + cb * 2);
                float2 win[8];
                #pragma unroll
                for (int c = 0; c < 8; c++) win[c] = xr[c];
                #pragma unroll
                for (int kx = 0; kx < 5; kx++)
                    #pragma unroll
                    for (int oc = 0; oc < 6; oc++) {
                        // ky=0 at components 1 (ic0) / 3 (ic1) of W1P[oc][0][kx]
                        int base = (((ocb + oc) * 4 + 0) * 5 + kx) * 4;
                        float wx = s[OFF_W1P + base + 1];
                        float wy = s[OFF_W1P + base + 3];
                        #pragma unroll
                        for (int c = 0; c < 4; c++) {
                            float a = a0s[oc * 4 + c];
                            a = fmaf(wx, win[kx + c].x, a);
                            a = fmaf(wy, win[kx + c].y, a);
                            a0s[oc * 4 + c] = a;
                        }
                    }
            }
            u64 P[24];
            #pragma unroll
            for (int k = 0; k < 24; k++) P[k] = pack2(a0s[k], 0.f);

            // --- ry = 1..4: paired (side0 ky=ry, side1 ky=ry-1) ---
            #pragma unroll
            for (int ry = 1; ry <= 4; ry++) {
                const float2* xr = reinterpret_cast<const float2*>(
                    xs + (2 * i1 + ry) * 66 + cb * 2);
                float2 win[8];
                #pragma unroll
                for (int c = 0; c < 8; c++) win[c] = xr[c];
                u64 xd[16];
                #pragma unroll
                for (int j = 0; j < 8; j++) {
                    xd[2 * j]     = pack2(win[j].x, win[j].x);
                    xd[2 * j + 1] = pack2(win[j].y, win[j].y);
                }
                #pragma unroll
                for (int kx = 0; kx < 5; kx++)
                    #pragma unroll
                    for (int oc = 0; oc < 6; oc++) {
                        ulonglong2 wq = *reinterpret_cast<const ulonglong2*>(
                            s + OFF_W1P +
                            (((ocb + oc) * 4 + (ry - 1)) * 5 + kx) * 4);
                        #pragma unroll
                        for (int c = 0; c < 4; c++) {
                            ffma2(P[oc * 4 + c], wq.x, xd[2 * (kx + c)]);
                            ffma2(P[oc * 4 + c], wq.y, xd[2 * (kx + c) + 1]);
                        }
                    }
            }
            float a1s[24];
            #pragma unroll
            for (int k = 0; k < 24; k++) unpack2(a0s[k], a1s[k], P[k]);

            // --- ry = 5: scalar, side1 (conv row 2i1+1, ky=4) ---
            {
                const float2* xr = reinterpret_cast<const float2*>(
                    xs + (2 * i1 + 5) * 66 + cb * 2);
                float2 win[8];
                #pragma unroll
                for (int c = 0; c < 8; c++) win[c] = xr[c];
                #pragma unroll
                for (int kx = 0; kx < 5; kx++)
                    #pragma unroll
                    for (int oc = 0; oc < 6; oc++) {
                        // ky=4 at components 0 (ic0) / 2 (ic1) of W1P[oc][3][kx]
                        int base = (((ocb + oc) * 4 + 3) * 5 + kx) * 4;
                        float wx = s[OFF_W1P + base + 0];
                        float wy = s[OFF_W1P + base + 2];
                        #pragma unroll
                        for (int c = 0; c < 4; c++) {
                            float a = a1s[oc * 4 + c];
                            a = fmaf(wx, win[kx + c].x, a);
                            a = fmaf(wy, win[kx + c].y, a);
                            a1s[oc * 4 + c] = a;
                        }
                    }
            }

            // pool + LIF + dual-layout spike stores
            #pragma unroll
            for (int oc = 0; oc < 6; oc++) {
                float p0 = fmaxf(fmaxf(a0s[oc*4+0], a0s[oc*4+1]),
                                 fmaxf(a1s[oc*4+0], a1s[oc*4+1]));
                float p1 = fmaxf(fmaxf(a0s[oc*4+2], a0s[oc*4+3]),
                                 fmaxf(a1s[oc*4+2], a1s[oc*4+3]));
                float bias = s[OFF_B1 + ocb + oc];
                float sp0 = lif_step(mem1r[oc * 2 + 0], __fadd_rn(p0, bias));
                float sp1 = lif_step(mem1r[oc * 2 + 1], __fadd_rn(p1, bias));
                const int r = i1, ch = ocb + oc;
                const int rpA = r >> 1, qA = r & 1;
                const int c0 = 2 * jp, c1 = 2 * jp + 1;
                s[OFF_S1A + ((c0 * 7 + rpA) * 12 + ch) * 2 + qA] = sp0;
                s[OFF_S1A + ((c1 * 7 + rpA) * 12 + ch) * 2 + qA] = sp1;
                if (r >= 1 && r <= 12) {
                    const int rpB = (r - 1) >> 1, qB = 1 - (r & 1);
                    s[OFF_S1B + ((c0 * 6 + rpB) * 12 + ch) * 2 + qB] = sp0;
                    s[OFF_S1B + ((c1 * 6 + rpB) * 12 + ch) * 2 + qB] = sp1;
                }
            }
        } else if (t + 1 < T_STEPS) {
            // --- threads 228-255 (idle otherwise): prefetch x(t+1) ---------
            // bulk LDG.128 + scattered STS into the alternate buffer; hidden
            // under stage1's FMA block; zero pressure on compute threads.
            const float4* gx4 = reinterpret_cast<const float4*>(
                x + ((long long)(t + 1) * BATCH + b) * 2048);
            float* xb = s + (((t + 1) & 1) ? OFF_X1 : OFF_X0);
            for (int q = tid - 228; q < 512; q += 28) {
                float4 v = gx4[q];
                x_scatter(xb, q, v);
            }
        }
        __syncthreads();

        // ===== phase B: stage 2 only (column-rolling FFMA2, lane = oc) =====
        {
            const float* wocb = s + OFF_W2 + lane * 300;
            u64 A0[4], A1[4];
            #pragma unroll
            for (int m = 0; m < 4; m++) { A0[m] = 0ULL; A1[m] = 0ULL; }

            for (int ky = 0; ky < 5; ky++) {
                const float* pb[4];
                int cs4[4];
                #pragma unroll
                for (int m = 0; m < 4; m++) {
                    int ra = 2 * pim[m] + ky;
                    if (ra & 1) {
                        cs4[m] = 144;
                        pb[m] = s + OFF_S1B + ((ra - 1) >> 1) * 24
                                + 2 * pjm[m] * 144;
                    } else {
                        cs4[m] = 168;
                        pb[m] = s + OFF_S1A + (ra >> 1) * 24
                                + 2 * pjm[m] * 168;
                    }
                }
                u64 wcur[12], wprev[12];
                #pragma unroll
                for (int j = 0; j < 12; j++) { wcur[j] = 0ULL; wprev[j] = 0ULL; }
                #pragma unroll
                for (int c = 0; c < 6; c++) {
                    #pragma unroll
                    for (int j = 0; j < 12; j++) wprev[j] = wcur[j];
                    if (c < 5) {
                        const float4* wv4 = reinterpret_cast<const float4*>(
                            wocb + (ky * 5 + c) * 12);
                        float4 w0 = wv4[0], w1 = wv4[1], w2 = wv4[2];
                        wcur[0]  = pack2(w0.x, w0.x); wcur[1]  = pack2(w0.y, w0.y);
                        wcur[2]  = pack2(w0.z, w0.z); wcur[3]  = pack2(w0.w, w0.w);
                        wcur[4]  = pack2(w1.x, w1.x); wcur[5]  = pack2(w1.y, w1.y);
                        wcur[6]  = pack2(w1.z, w1.z); wcur[7]  = pack2(w1.w, w1.w);
                        wcur[8]  = pack2(w2.x, w2.x); wcur[9]  = pack2(w2.y, w2.y);
                        wcur[10] = pack2(w2.z, w2.z); wcur[11] = pack2(w2.w, w2.w);
                    }
                    #pragma unroll
                    for (int m = 0; m < 4; m++) {
                        if (m < 3 || has4) {
                            const ulonglong2* xc =
                                reinterpret_cast<const ulonglong2*>(
                                    pb[m] + c * cs4[m]);
                            ulonglong2 x0 = xc[0], x1 = xc[1], x2 = xc[2];
                            ulonglong2 x3 = xc[3], x4 = xc[4], x5 = xc[5];
                            if (c < 5) {
                                ffma2(A0[m], wcur[0],  x0.x);
                                ffma2(A0[m], wcur[1],  x0.y);
                                ffma2(A0[m], wcur[2],  x1.x);
                                ffma2(A0[m], wcur[3],  x1.y);
                                ffma2(A0[m], wcur[4],  x2.x);
                                ffma2(A0[m], wcur[5],  x2.y);
                                ffma2(A0[m], wcur[6],  x3.x);
                                ffma2(A0[m], wcur[7],  x3.y);
                                ffma2(A0[m], wcur[8],  x4.x);
                                ffma2(A0[m], wcur[9],  x4.y);
                                ffma2(A0[m], wcur[10], x5.x);
                                ffma2(A0[m], wcur[11], x5.y);
                            }
                            if (c >= 1) {
                                ffma2(A1[m], wprev[0],  x0.x);
                                ffma2(A1[m], wprev[1],  x0.y);
                                ffma2(A1[m], wprev[2],  x1.x);
                                ffma2(A1[m], wprev[3],  x1.y);
                                ffma2(A1[m], wprev[4],  x2.x);
                                ffma2(A1[m], wprev[5],  x2.y);
                                ffma2(A1[m], wprev[6],  x3.x);
                                ffma2(A1[m], wprev[7],  x3.y);
                                ffma2(A1[m], wprev[8],  x4.x);
                                ffma2(A1[m], wprev[9],  x4.y);
                                ffma2(A1[m], wprev[10], x5.x);
                                ffma2(A1[m], wprev[11], x5.y);
                            }
                        }
                    }
                }
            }
            #pragma unroll
            for (int m = 0; m < 4; m++) {
                if (m < 3 || has4) {
                    int p = (m < 3) ? (8 * m + w) : 24;
                    float a00, a10, a01, a11;
                    unpack2(a00, a10, A0[m]);
                    unpack2(a01, a11, A1[m]);
                    float pm = fmaxf(fmaxf(a00, a01), fmaxf(a10, a11));
                    float cur = __fadd_rn(pm, s[OFF_B2 + lane]);
                    s[OFF_S2 + lane * 25 + p] = lif_step(mem2r[m], cur);
                }
            }
        }
        __syncthreads();
    }

    if (w == 0 && lane < 10)
        fc_stage(s, mem3r, T_STEPS - 1, b, lane, out);
}

extern "C" void kernel_launch(void* const* d_in, const int* in_sizes, int n_in,
                              void* d_out, int out_size) {
    const float* x  = (const float*)d_in[0];
    const float* W1 = (const float*)d_in[1];
    const float* b1 = (const float*)d_in[2];
    const float* W2 = (const float*)d_in[3];
    const float* b2 = (const float*)d_in[4];
    const float* W3 = (const float*)d_in[5];
    const float* b3 = (const float*)d_in[6];
    float* out = (float*)d_out;

    cudaFuncSetAttribute(snn_kernel,
                         cudaFuncAttributeMaxDynamicSharedMemorySize,
                         SMEM_BYTES);
    snn_kernel<<<BATCH, 256, SMEM_BYTES>>>(x, W1, b1, W2, b2, W3, b3, out);
}

// round 12
// speedup vs baseline: 1.3682x; 1.3682x over previous
#include <cuda_runtime.h>

// ---------------------------------------------------------------------------
// Bit-exact fused SNN kernel, v10 = v5 (best, 2024us) + stage1 ocg-by-half
// task remap: all lanes of a warp share the same oc-group, turning every
// stage1 weight load (W1P ulonglong2 / W1 float2) into a warp-uniform
// broadcast (1 wavefront) instead of lane-alternating (~4 wavefronts).
// No prefetch (R8-R11 all regressed); serial x-load as in v5.
// PROTECTED arithmetic (rel_err == 0.0 invariant):
//   conv: per-output sequential FMA in (ky, kx, ic) order
//   FC:   sequential FMA q = 0..799
//   LIF:  m' = fsub(fma(0.95, m, cur), reset)
//   pool-then-bias
// FFMA2 = two INDEPENDENT IEEE fma.rn; pairing never mixes chains.
// ---------------------------------------------------------------------------

#define T_STEPS 100
#define BATCH   256

typedef unsigned long long u64;

// smem layout (float offsets)
constexpr int OFF_W1  = 0;       // w1 cl [oc][ky][kx][ic2]          = 600
constexpr int OFF_B1  = 600;     // 12 (+4 pad)
constexpr int OFF_W1P = 616;     // paired w1 [oc][ry-1][kx][4]      = 960
constexpr int OFF_W2  = 1576;    // w2 cl [32][25][12]               = 9600
constexpr int OFF_B2  = 11176;   // 32
constexpr int OFF_W3  = 11208;   // [10][804]                        = 8040
constexpr int OFF_B3  = 19248;   // 12
constexpr int OFF_X   = 19260;   // x cl [32 rows][66]               = 2112
constexpr int OFF_S1A = 21372;   // spk1 A [col14][rp7][ic12][2]     = 2352
constexpr int OFF_S1B = 23724;   // spk1 B [col14][rp6][ic12][2]     = 2016
constexpr int OFF_S2  = 25740;   // 800 (oc*25 + i*5 + j)
constexpr int SMEM_FLOATS = 26540;
constexpr int SMEM_BYTES  = SMEM_FLOATS * 4;

__device__ __forceinline__ u64 pack2(float lo, float hi) {
    u64 r;
    asm("mov.b64 %0, {%1, %2};" : "=l"(r) : "f"(lo), "f"(hi));
    return r;
}
__device__ __forceinline__ void unpack2(float& lo, float& hi, u64 v) {
    asm("mov.b64 {%0, %1}, %2;" : "=f"(lo), "=f"(hi) : "l"(v));
}
// d.lo = fma.rn(a.lo, b.lo, d.lo); d.hi = fma.rn(a.hi, b.hi, d.hi)
__device__ __forceinline__ void ffma2(u64& d, u64 a, u64 b) {
    asm("fma.rn.f32x2 %0, %1, %2, %0;" : "+l"(d) : "l"(a), "l"(b));
}

__device__ __forceinline__ float lif_step(float& mem, float cur) {
    float reset = (mem > 1.0f) ? 1.0f : 0.0f;
    float mn = __fsub_rn(__fmaf_rn(0.95f, mem, cur), reset);
    mem = mn;
    return (mn > 1.0f) ? 1.0f : 0.0f;
}

__device__ __forceinline__ void fc_stage(const float* __restrict__ s,
                                         float& mem3, int t, int b, int k,
                                         float* __restrict__ out) {
    const float4* wr = reinterpret_cast<const float4*>(s + OFF_W3 + k * 804);
    const float4* xv = reinterpret_cast<const float4*>(s + OFF_S2);
    float acc = 0.f;
    #pragma unroll 4
    for (int q = 0; q < 200; q++) {
        float4 w = wr[q], x = xv[q];
        acc = fmaf(x.x, w.x, acc);
        acc = fmaf(x.y, w.y, acc);
        acc = fmaf(x.z, w.z, acc);
        acc = fmaf(x.w, w.w, acc);
    }
    float cur = __fadd_rn(acc, s[OFF_B3 + k]);
    out[((long long)t * BATCH + b) * 10 + k] = lif_step(mem3, cur);
}

__global__ void __launch_bounds__(256, 2) snn_kernel(
    const float* __restrict__ x,
    const float* __restrict__ W1, const float* __restrict__ b1,
    const float* __restrict__ W2, const float* __restrict__ b2,
    const float* __restrict__ W3, const float* __restrict__ b3,
    float* __restrict__ out)
{
    extern __shared__ float s[];
    const int b    = blockIdx.x;
    const int tid  = threadIdx.x;
    const int lane = tid & 31;
    const int w    = tid >> 5;

    // --- weights -> smem ---
    for (int i = tid; i < 600; i += 256) {
        int oc = i / 50, r = i % 50, ic = r / 25, k = r % 25;
        s[OFF_W1 + (oc * 25 + k) * 2 + ic] = W1[i];
    }
    // paired conv1 weights: [oc][ry-1][kx][{(ry,ic0),(ry-1,ic0),(ry,ic1),(ry-1,ic1)}]
    for (int i = tid; i < 960; i += 256) {
        int q = i & 3, idx = i >> 2;
        int kx = idx % 5, ryp = (idx / 5) % 4, oc = idx / 20;
        int ry = ryp + 1;
        int ic = q >> 1;
        int useKy = (q & 1) ? (ry - 1) : ry;
        s[OFF_W1P + i] = W1[oc * 50 + ic * 25 + useKy * 5 + kx];
    }
    for (int i = tid; i < 9600; i += 256) {
        int oc = i / 300, r = i % 300, ic = r / 25, k = r % 25;
        s[OFF_W2 + oc * 300 + k * 12 + ic] = W2[i];
    }
    for (int i = tid; i < 8000; i += 256) {
        int k = i / 800, q = i % 800;
        s[OFF_W3 + k * 804 + q] = W3[i];
    }
    for (int i = tid; i < 12; i += 256) s[OFF_B1 + i] = b1[i];
    for (int i = tid; i < 32; i += 256) s[OFF_B2 + i] = b2[i];
    for (int i = tid; i < 12; i += 256) s[OFF_B3 + i] = (i < 10) ? b3[i] : 0.f;
    __syncthreads();

    float mem1r[12];
    #pragma unroll
    for (int k = 0; k < 12; k++) mem1r[k] = 0.f;
    float mem2r[4];
    #pragma unroll
    for (int k = 0; k < 4; k++) mem2r[k] = 0.f;
    float mem3r = 0.f;

    // stage2 positions: m<3 -> p = 8m + w; m=3 -> p=24, warp 7 only
    const bool has4 = (w == 7);
    int pim[4], pjm[4];
    #pragma unroll
    for (int m = 0; m < 4; m++) {
        int p = (m < 3) ? (8 * m + w) : 24;
        pim[m] = p / 5;
        pjm[m] = p % 5;
    }

    for (int t = 0; t < T_STEPS; t++) {
        // ============ phase A: FC(t-1) on warp0 || x-load + stage1 =========
        if (w == 0) {
            if (t > 0 && lane < 10) fc_stage(s, mem3r, t - 1, b, lane, out);
        } else {
            const float* xg = x + ((long long)t * BATCH + b) * 2048;
            for (int idx = tid - 32; idx < 2048; idx += 224) {
                int ic = idx >> 10, pos = idx & 1023;
                int r = pos >> 5, c = pos & 31;
                s[OFF_X + r * 66 + c * 2 + ic] = xg[idx];
            }
            asm volatile("bar.sync 1, 224;" ::: "memory");

            if (tid < 228) {
                // ocg by thread-half: threads 32..129 -> ocg 0, pos 0..97;
                // threads 130..227 -> ocg 1, pos 0..97. Warp-uniform ocb ->
                // all weight loads broadcast (1 wavefront).
                const int task = tid - 32;
                const int ocg = (task < 98) ? 0 : 1;
                const int pos = (task < 98) ? task : (task - 98);
                const int i1 = pos / 7, jp = pos % 7;
                const int cb = 4 * jp;
                const int ocb = ocg * 6;

                // --- ry = 0: scalar, side0 (conv row 2i1, ky=0) ---
                float a0s[24];
                #pragma unroll
                for (int k = 0; k < 24; k++) a0s[k] = 0.f;
                {
                    const float2* xr = reinterpret_cast<const float2*>(
                        s + OFF_X + (2 * i1) * 66 + cb * 2);
                    float2 win[8];
                    #pragma unroll
                    for (int c = 0; c < 8; c++) win[c] = xr[c];
                    #pragma unroll
                    for (int kx = 0; kx < 5; kx++)
                        #pragma unroll
                        for (int oc = 0; oc < 6; oc++) {
                            float2 wv = *reinterpret_cast<const float2*>(
                                s + OFF_W1 + ((ocb + oc) * 25 + kx) * 2);
                            #pragma unroll
                            for (int c = 0; c < 4; c++) {
                                float a = a0s[oc * 4 + c];
                                a = fmaf(wv.x, win[kx + c].x, a);
                                a = fmaf(wv.y, win[kx + c].y, a);
                                a0s[oc * 4 + c] = a;
                            }
                        }
                }
                u64 P[24];
                #pragma unroll
                for (int k = 0; k < 24; k++) P[k] = pack2(a0s[k], 0.f);

                // --- ry = 1..4: paired (side0 ky=ry, side1 ky=ry-1) ---
                #pragma unroll
                for (int ry = 1; ry <= 4; ry++) {
                    const float2* xr = reinterpret_cast<const float2*>(
                        s + OFF_X + (2 * i1 + ry) * 66 + cb * 2);
                    float2 win[8];
                    #pragma unroll
                    for (int c = 0; c < 8; c++) win[c] = xr[c];
                    u64 xd[16];
                    #pragma unroll
                    for (int j = 0; j < 8; j++) {
                        xd[2 * j]     = pack2(win[j].x, win[j].x);
                        xd[2 * j + 1] = pack2(win[j].y, win[j].y);
                    }
                    #pragma unroll
                    for (int kx = 0; kx < 5; kx++)
                        #pragma unroll
                        for (int oc = 0; oc < 6; oc++) {
                            ulonglong2 wq = *reinterpret_cast<const ulonglong2*>(
                                s + OFF_W1P +
                                (((ocb + oc) * 4 + (ry - 1)) * 5 + kx) * 4);
                            #pragma unroll
                            for (int c = 0; c < 4; c++) {
                                ffma2(P[oc * 4 + c], wq.x, xd[2 * (kx + c)]);
                                ffma2(P[oc * 4 + c], wq.y, xd[2 * (kx + c) + 1]);
                            }
                        }
                }
                float a1s[24];
                #pragma unroll
                for (int k = 0; k < 24; k++) unpack2(a0s[k], a1s[k], P[k]);

                // --- ry = 5: scalar, side1 (conv row 2i1+1, ky=4) ---
                {
                    const float2* xr = reinterpret_cast<const float2*>(
                        s + OFF_X + (2 * i1 + 5) * 66 + cb * 2);
                    float2 win[8];
                    #pragma unroll
                    for (int c = 0; c < 8; c++) win[c] = xr[c];
                    #pragma unroll
                    for (int kx = 0; kx < 5; kx++)
                        #pragma unroll
                        for (int oc = 0; oc < 6; oc++) {
                            float2 wv = *reinterpret_cast<const float2*>(
                                s + OFF_W1 + ((ocb + oc) * 25 + 20 + kx) * 2);
                            #pragma unroll
                            for (int c = 0; c < 4; c++) {
                                float a = a1s[oc * 4 + c];
                                a = fmaf(wv.x, win[kx + c].x, a);
                                a = fmaf(wv.y, win[kx + c].y, a);
                                a1s[oc * 4 + c] = a;
                            }
                        }
                }

                // pool + LIF + dual-layout spike stores
                #pragma unroll
                for (int oc = 0; oc < 6; oc++) {
                    float p0 = fmaxf(fmaxf(a0s[oc*4+0], a0s[oc*4+1]),
                                     fmaxf(a1s[oc*4+0], a1s[oc*4+1]));
                    float p1 = fmaxf(fmaxf(a0s[oc*4+2], a0s[oc*4+3]),
                                     fmaxf(a1s[oc*4+2], a1s[oc*4+3]));
                    float bias = s[OFF_B1 + ocb + oc];
                    float sp0 = lif_step(mem1r[oc * 2 + 0], __fadd_rn(p0, bias));
                    float sp1 = lif_step(mem1r[oc * 2 + 1], __fadd_rn(p1, bias));
                    const int r = i1, ch = ocb + oc;
                    const int rpA = r >> 1, qA = r & 1;
                    const int c0 = 2 * jp, c1 = 2 * jp + 1;
                    s[OFF_S1A + ((c0 * 7 + rpA) * 12 + ch) * 2 + qA] = sp0;
                    s[OFF_S1A + ((c1 * 7 + rpA) * 12 + ch) * 2 + qA] = sp1;
                    if (r >= 1 && r <= 12) {
                        const int rpB = (r - 1) >> 1, qB = 1 - (r & 1);
                        s[OFF_S1B + ((c0 * 6 + rpB) * 12 + ch) * 2 + qB] = sp0;
                        s[OFF_S1B + ((c1 * 6 + rpB) * 12 + ch) * 2 + qB] = sp1;
                    }
                }
            }
        }
        __syncthreads();

        // ============ phase B: stage 2, column-rolling FFMA2 ===============
        {
            const float* wocb = s + OFF_W2 + lane * 300;
            u64 A0[4], A1[4];
            #pragma unroll
            for (int m = 0; m < 4; m++) { A0[m] = 0ULL; A1[m] = 0ULL; }

            for (int ky = 0; ky < 5; ky++) {
                const float* pb[4];
                int cs4[4];
                #pragma unroll
                for (int m = 0; m < 4; m++) {
                    int ra = 2 * pim[m] + ky;
                    if (ra & 1) {
                        cs4[m] = 144;
                        pb[m] = s + OFF_S1B + ((ra - 1) >> 1) * 24
                                + 2 * pjm[m] * 144;
                    } else {
                        cs4[m] = 168;
                        pb[m] = s + OFF_S1A + (ra >> 1) * 24
                                + 2 * pjm[m] * 168;
                    }
                }
                u64 wcur[12], wprev[12];
                #pragma unroll
                for (int j = 0; j < 12; j++) { wcur[j] = 0ULL; wprev[j] = 0ULL; }
                #pragma unroll
                for (int c = 0; c < 6; c++) {
                    #pragma unroll
                    for (int j = 0; j < 12; j++) wprev[j] = wcur[j];
                    if (c < 5) {
                        const float4* wv4 = reinterpret_cast<const float4*>(
                            wocb + (ky * 5 + c) * 12);
                        float4 w0 = wv4[0], w1 = wv4[1], w2 = wv4[2];
                        wcur[0]  = pack2(w0.x, w0.x); wcur[1]  = pack2(w0.y, w0.y);
                        wcur[2]  = pack2(w0.z, w0.z); wcur[3]  = pack2(w0.w, w0.w);
                        wcur[4]  = pack2(w1.x, w1.x); wcur[5]  = pack2(w1.y, w1.y);
                        wcur[6]  = pack2(w1.z, w1.z); wcur[7]  = pack2(w1.w, w1.w);
                        wcur[8]  = pack2(w2.x, w2.x); wcur[9]  = pack2(w2.y, w2.y);
                        wcur[10] = pack2(w2.z, w2.z); wcur[11] = pack2(w2.w, w2.w);
                    }
                    #pragma unroll
                    for (int m = 0; m < 4; m++) {
                        if (m < 3 || has4) {
                            const ulonglong2* xc =
                                reinterpret_cast<const ulonglong2*>(
                                    pb[m] + c * cs4[m]);
                            ulonglong2 x0 = xc[0], x1 = xc[1], x2 = xc[2];
                            ulonglong2 x3 = xc[3], x4 = xc[4], x5 = xc[5];
                            if (c < 5) {
                                ffma2(A0[m], wcur[0],  x0.x);
                                ffma2(A0[m], wcur[1],  x0.y);
                                ffma2(A0[m], wcur[2],  x1.x);
                                ffma2(A0[m], wcur[3],  x1.y);
                                ffma2(A0[m], wcur[4],  x2.x);
                                ffma2(A0[m], wcur[5],  x2.y);
                                ffma2(A0[m], wcur[6],  x3.x);
                                ffma2(A0[m], wcur[7],  x3.y);
                                ffma2(A0[m], wcur[8],  x4.x);
                                ffma2(A0[m], wcur[9],  x4.y);
                                ffma2(A0[m], wcur[10], x5.x);
                                ffma2(A0[m], wcur[11], x5.y);
                            }
                            if (c >= 1) {
                                ffma2(A1[m], wprev[0],  x0.x);
                                ffma2(A1[m], wprev[1],  x0.y);
                                ffma2(A1[m], wprev[2],  x1.x);
                                ffma2(A1[m], wprev[3],  x1.y);
                                ffma2(A1[m], wprev[4],  x2.x);
                                ffma2(A1[m], wprev[5],  x2.y);
                                ffma2(A1[m], wprev[6],  x3.x);
                                ffma2(A1[m], wprev[7],  x3.y);
                                ffma2(A1[m], wprev[8],  x4.x);
                                ffma2(A1[m], wprev[9],  x4.y);
                                ffma2(A1[m], wprev[10], x5.x);
                                ffma2(A1[m], wprev[11], x5.y);
                            }
                        }
                    }
                }
            }
            #pragma unroll
            for (int m = 0; m < 4; m++) {
                if (m < 3 || has4) {
                    int p = (m < 3) ? (8 * m + w) : 24;
                    float a00, a10, a01, a11;
                    unpack2(a00, a10, A0[m]);
                    unpack2(a01, a11, A1[m]);
                    float pm = fmaxf(fmaxf(a00, a01), fmaxf(a10, a11));
                    float cur = __fadd_rn(pm, s[OFF_B2 + lane]);
                    s[OFF_S2 + lane * 25 + p] = lif_step(mem2r[m], cur);
                }
            }
        }
        __syncthreads();
    }

    if (w == 0 && lane < 10)
        fc_stage(s, mem3r, T_STEPS - 1, b, lane, out);
}

extern "C" void kernel_launch(void* const* d_in, const int* in_sizes, int n_in,
                              void* d_out, int out_size) {
    const float* x  = (const float*)d_in[0];
    const float* W1 = (const float*)d_in[1];
    const float* b1 = (const float*)d_in[2];
    const float* W2 = (const float*)d_in[3];
    const float* b2 = (const float*)d_in[4];
    const float* W3 = (const float*)d_in[5];
    const float* b3 = (const float*)d_in[6];
    float* out = (float*)d_out;

    cudaFuncSetAttribute(snn_kernel,
                         cudaFuncAttributeMaxDynamicSharedMemorySize,
                         SMEM_BYTES);
    snn_kernel<<<BATCH, 256, SMEM_BYTES>>>(x, W1, b1, W2, b2, W3, b3, out);
}